// round 14
// baseline (speedup 1.0000x reference)
#include <cuda_runtime.h>

// Problem constants
#define B_  4
#define C_  32
#define H_  720
#define W_  720
#define HW_ (H_ * W_)      // 518400
#define HW4_ (HW_ / 4)     // 129600
#define W4_ (W_ / 4)       // 180
#define PAD_ 4

// Scratch: channel sum (pre-divided by 9). 8.3 MB -> L2-resident.
__device__ float g_s[B_ * HW_];

// ---------------------------------------------------------------------------
// Kernel 1: s[b,h,w] = (1/9) * sum_c x[b,c,h,w].  float4 streaming, 265 MB read.
// __ldcs: x is read exactly once; don't let it evict s from L2.
// ---------------------------------------------------------------------------
__global__ void chansum_kernel(const float* __restrict__ x) {
    int idx = blockIdx.x * blockDim.x + threadIdx.x;   // 0 .. B*HW4-1
    if (idx >= B_ * HW4_) return;
    int b = idx / HW4_;
    int p = idx - b * HW4_;

    const float4* x4 = reinterpret_cast<const float4*>(x);
    const float4* base = x4 + (long long)b * C_ * HW4_ + p;

    float4 acc = make_float4(0.f, 0.f, 0.f, 0.f);
    #pragma unroll
    for (int c = 0; c < C_; ++c) {
        float4 v = __ldcs(base + (long long)c * HW4_);
        acc.x += v.x; acc.y += v.y; acc.z += v.z; acc.w += v.w;
    }
    const float inv9 = 1.0f / 9.0f;
    acc.x *= inv9; acc.y *= inv9; acc.z *= inv9; acc.w *= inv9;
    reinterpret_cast<float4*>(g_s)[idx] = acc;
}

// ---------------------------------------------------------------------------
// Kernel 2 (fused): per block (b,h):
//   - compute W2[o,kh] = sum_c conv_w[o,c,kh,0] into smem (conv_w is 12 KB,
//     L1/L2-resident after block 0 — hides under the staging loads below)
//   - stage s rows h-5..h+5, logical cols -4..723 into smem (zero-padded)
//   - compute dm = D(h-1,.), d0 = D(h,.), dp = D(h+1,.) where
//     D(h',w) = sum_{δ=-4..4} s[h'+δ, w+δ]  (zero outside the image)
//   - out[b,o,h,w] = W2[o,0]*dm + W2[o,1]*d0 + W2[o,2]*dp  (dm/dp zero at H edges)
//
// Smem row stride 728 floats; cols 0..3 and 724..727 are permanent zeros
// (they map to out-of-range image columns). Each thread owns 4 w's and reads
// 3 aligned float4 per staged row -> conflict-free LDS.128, static-index adds.
// ---------------------------------------------------------------------------
#define SROW_ 728
__global__ __launch_bounds__(192) void fused_epilogue_kernel(
        const float* __restrict__ conv_w, float* __restrict__ out) {
    __shared__ float S[11 * SROW_];     // 32,032 B
    __shared__ float sw2[C_ * 3];

    int tid = threadIdx.x;              // 0..191
    int h = blockIdx.x;                 // 0..719
    int b = blockIdx.y;                 // 0..3

    // per-block W2 reduction (replaces the former w2_kernel launch)
    if (tid < C_ * 3) {
        int o = tid / 3;
        int kh = tid - o * 3;
        float acc = 0.f;
        #pragma unroll
        for (int c = 0; c < C_; ++c)
            acc += __ldg(&conv_w[o * (C_ * 3) + c * 3 + kh]);
        sw2[tid] = acc;
    }

    // zero the 8 edge columns of each of the 11 rows (88 items)
    if (tid >= 96 && tid < 96 + 88) {
        int e8 = tid - 96;
        int r = e8 / 8;
        int e = e8 - r * 8;
        int c = (e < 4) ? e : (720 + e);   // cols 0..3 and 724..727
        S[r * SROW_ + c] = 0.f;
    }

    // stage 11 rows: smem col 4+4k <- global col 4k (float4, 16B-aligned)
    const float4* s4 = reinterpret_cast<const float4*>(g_s);
    if (tid < W4_) {
        #pragma unroll
        for (int r = 0; r < 11; ++r) {
            int row = h - 5 + r;
            float4 v = make_float4(0.f, 0.f, 0.f, 0.f);
            if ((unsigned)row < (unsigned)H_)
                v = s4[(long long)b * HW4_ + (long long)row * W4_ + tid];
            *reinterpret_cast<float4*>(&S[r * SROW_ + 4 + 4 * tid]) = v;
        }
    }
    __syncthreads();

    if (tid >= W4_) return;

    // accumulate the three diagonal rows
    float am[4] = {0.f, 0.f, 0.f, 0.f};   // dm = D(h-1,.)
    float a0[4] = {0.f, 0.f, 0.f, 0.f};   // d0 = D(h,.)
    float ap[4] = {0.f, 0.f, 0.f, 0.f};   // dp = D(h+1,.)

    #pragma unroll
    for (int lr = 0; lr < 11; ++lr) {
        // load 12 consecutive floats: smem cols 4*tid .. 4*tid+11 of row lr
        const float* rowp = &S[lr * SROW_ + 4 * tid];
        float4 v0 = *reinterpret_cast<const float4*>(rowp + 0);
        float4 v1 = *reinterpret_cast<const float4*>(rowp + 4);
        float4 v2 = *reinterpret_cast<const float4*>(rowp + 8);
        float v[12] = {v0.x, v0.y, v0.z, v0.w,
                       v1.x, v1.y, v1.z, v1.w,
                       v2.x, v2.y, v2.z, v2.w};
        // row lr holds s[h-5+lr]. Contributions (k = j + δ + 4, col = 4*tid + k):
        //   dm: δ = lr-4 (rows 0..8)  -> k = j + lr
        //   d0: δ = lr-5 (rows 1..9)  -> k = j + lr - 1
        //   dp: δ = lr-6 (rows 2..10) -> k = j + lr - 2
        #pragma unroll
        for (int j = 0; j < 4; ++j) {
            if (lr <= 8)            am[j] += v[j + lr];
            if (lr >= 1 && lr <= 9) a0[j] += v[j + lr - 1];
            if (lr >= 2)            ap[j] += v[j + lr - 2];
        }
    }

    // conv zero-padding in H for the 3x1 conv
    if (h == 0) {
        am[0] = am[1] = am[2] = am[3] = 0.f;
    }
    if (h == H_ - 1) {
        ap[0] = ap[1] = ap[2] = ap[3] = 0.f;
    }

    float4* out4 = reinterpret_cast<float4*>(out);
    long long obase = ((long long)b * C_ * H_ + h) * W4_ + tid;
    #pragma unroll 8
    for (int o = 0; o < C_; ++o) {
        float w0 = sw2[o * 3 + 0];
        float w1 = sw2[o * 3 + 1];
        float w2 = sw2[o * 3 + 2];
        float4 r;
        r.x = w0 * am[0] + w1 * a0[0] + w2 * ap[0];
        r.y = w0 * am[1] + w1 * a0[1] + w2 * ap[1];
        r.z = w0 * am[2] + w1 * a0[2] + w2 * ap[2];
        r.w = w0 * am[3] + w1 * a0[3] + w2 * ap[3];
        __stcs(&out4[obase + (long long)o * HW4_], r);
    }
}

// ---------------------------------------------------------------------------
extern "C" void kernel_launch(void* const* d_in, const int* in_sizes, int n_in,
                              void* d_out, int out_size) {
    const float* x      = (const float*)d_in[0];   // [4,32,720,720] f32
    const float* conv_w = (const float*)d_in[1];   // [32,32,3,1] f32
    float* out          = (float*)d_out;           // [4,32,720,720] f32

    (void)in_sizes; (void)n_in; (void)out_size;

    {
        int n = B_ * HW4_;                          // 518400
        chansum_kernel<<<(n + 255) / 256, 256>>>(x);
    }
    {
        dim3 grid(H_, B_);
        fused_epilogue_kernel<<<grid, 192>>>(conv_w, out);
    }
}

// round 15
// speedup vs baseline: 1.0738x; 1.0738x over previous
#include <cuda_runtime.h>

// Problem constants
#define B_  4
#define C_  32
#define H_  720
#define W_  720
#define HW_ (H_ * W_)      // 518400
#define HW4_ (HW_ / 4)     // 129600
#define W4_ (W_ / 4)       // 180
#define PAD_ 4

#define CHANSUM_BLOCKS ((B_ * HW4_ + 255) / 256)   // 2025

// Scratch: channel sum (pre-divided by 9). 8.3 MB -> L2-resident.
__device__ float g_s[B_ * HW_];
__device__ float g_W2[C_ * 3];   // W2[o,kh] = sum_c conv_w[o,c,kh,0]

// ---------------------------------------------------------------------------
// Kernel 1: s[b,h,w] = (1/9) * sum_c x[b,c,h,w].  float4 streaming, 265 MB read.
// __ldcs: x is read exactly once; don't let it evict s from L2.
// The LAST block (index CHANSUM_BLOCKS) instead collapses conv_w over input
// channels into g_W2 — piggybacked so no separate launch is serialized.
// ---------------------------------------------------------------------------
__global__ void chansum_kernel(const float* __restrict__ x,
                               const float* __restrict__ conv_w) {
    if (blockIdx.x == CHANSUM_BLOCKS) {
        int t = threadIdx.x;          // t = o*3 + kh, 0..95
        if (t < C_ * 3) {
            int o = t / 3;
            int kh = t - o * 3;
            float acc = 0.f;
            #pragma unroll
            for (int c = 0; c < C_; ++c)
                acc += conv_w[o * (C_ * 3) + c * 3 + kh];
            g_W2[t] = acc;
        }
        return;
    }

    int idx = blockIdx.x * blockDim.x + threadIdx.x;   // 0 .. B*HW4-1
    if (idx >= B_ * HW4_) return;
    int b = idx / HW4_;
    int p = idx - b * HW4_;

    const float4* x4 = reinterpret_cast<const float4*>(x);
    const float4* base = x4 + (long long)b * C_ * HW4_ + p;

    float4 acc = make_float4(0.f, 0.f, 0.f, 0.f);
    #pragma unroll
    for (int c = 0; c < C_; ++c) {
        float4 v = __ldcs(base + (long long)c * HW4_);
        acc.x += v.x; acc.y += v.y; acc.z += v.z; acc.w += v.w;
    }
    const float inv9 = 1.0f / 9.0f;
    acc.x *= inv9; acc.y *= inv9; acc.z *= inv9; acc.w *= inv9;
    reinterpret_cast<float4*>(g_s)[idx] = acc;
}

// ---------------------------------------------------------------------------
// Kernel 2 (fused): per block (b,h):
//   - stage s rows h-5..h+5, logical cols -4..723 into smem (zero-padded)
//   - compute dm = D(h-1,.), d0 = D(h,.), dp = D(h+1,.) where
//     D(h',w) = sum_{δ=-4..4} s[h'+δ, w+δ]  (zero outside the image)
//   - out[b,o,h,w] = W2[o,0]*dm + W2[o,1]*d0 + W2[o,2]*dp  (dm/dp zero at H edges)
//
// Smem row stride 728 floats; cols 0..3 and 724..727 are permanent zeros
// (they map to out-of-range image columns). Each thread owns 4 w's and reads
// 3 aligned float4 per staged row -> conflict-free LDS.128, static-index adds.
// ---------------------------------------------------------------------------
#define SROW_ 728
__global__ __launch_bounds__(192) void fused_epilogue_kernel(float* __restrict__ out) {
    __shared__ float S[11 * SROW_];     // 32,032 B
    __shared__ float sw2[C_ * 3];

    int tid = threadIdx.x;              // 0..191
    int h = blockIdx.x;                 // 0..719
    int b = blockIdx.y;                 // 0..3

    if (tid < C_ * 3) sw2[tid] = g_W2[tid];   // single coalesced 384B load

    // zero the 8 edge columns of each of the 11 rows (88 items)
    if (tid >= 96 && tid < 96 + 88) {
        int e8 = tid - 96;
        int r = e8 / 8;
        int e = e8 - r * 8;
        int c = (e < 4) ? e : (720 + e);   // cols 0..3 and 724..727
        S[r * SROW_ + c] = 0.f;
    }

    // stage 11 rows: smem col 4+4k <- global col 4k (float4, 16B-aligned)
    const float4* s4 = reinterpret_cast<const float4*>(g_s);
    if (tid < W4_) {
        #pragma unroll
        for (int r = 0; r < 11; ++r) {
            int row = h - 5 + r;
            float4 v = make_float4(0.f, 0.f, 0.f, 0.f);
            if ((unsigned)row < (unsigned)H_)
                v = s4[(long long)b * HW4_ + (long long)row * W4_ + tid];
            *reinterpret_cast<float4*>(&S[r * SROW_ + 4 + 4 * tid]) = v;
        }
    }
    __syncthreads();

    if (tid >= W4_) return;

    // accumulate the three diagonal rows
    float am[4] = {0.f, 0.f, 0.f, 0.f};   // dm = D(h-1,.)
    float a0[4] = {0.f, 0.f, 0.f, 0.f};   // d0 = D(h,.)
    float ap[4] = {0.f, 0.f, 0.f, 0.f};   // dp = D(h+1,.)

    #pragma unroll
    for (int lr = 0; lr < 11; ++lr) {
        // load 12 consecutive floats: smem cols 4*tid .. 4*tid+11 of row lr
        const float* rowp = &S[lr * SROW_ + 4 * tid];
        float4 v0 = *reinterpret_cast<const float4*>(rowp + 0);
        float4 v1 = *reinterpret_cast<const float4*>(rowp + 4);
        float4 v2 = *reinterpret_cast<const float4*>(rowp + 8);
        float v[12] = {v0.x, v0.y, v0.z, v0.w,
                       v1.x, v1.y, v1.z, v1.w,
                       v2.x, v2.y, v2.z, v2.w};
        // row lr holds s[h-5+lr]. Contributions (k = j + δ + 4, col = 4*tid + k):
        //   dm: δ = lr-4 (rows 0..8)  -> k = j + lr
        //   d0: δ = lr-5 (rows 1..9)  -> k = j + lr - 1
        //   dp: δ = lr-6 (rows 2..10) -> k = j + lr - 2
        #pragma unroll
        for (int j = 0; j < 4; ++j) {
            if (lr <= 8)            am[j] += v[j + lr];
            if (lr >= 1 && lr <= 9) a0[j] += v[j + lr - 1];
            if (lr >= 2)            ap[j] += v[j + lr - 2];
        }
    }

    // conv zero-padding in H for the 3x1 conv
    if (h == 0) {
        am[0] = am[1] = am[2] = am[3] = 0.f;
    }
    if (h == H_ - 1) {
        ap[0] = ap[1] = ap[2] = ap[3] = 0.f;
    }

    float4* out4 = reinterpret_cast<float4*>(out);
    long long obase = ((long long)b * C_ * H_ + h) * W4_ + tid;
    #pragma unroll 8
    for (int o = 0; o < C_; ++o) {
        float w0 = sw2[o * 3 + 0];
        float w1 = sw2[o * 3 + 1];
        float w2 = sw2[o * 3 + 2];
        float4 r;
        r.x = w0 * am[0] + w1 * a0[0] + w2 * ap[0];
        r.y = w0 * am[1] + w1 * a0[1] + w2 * ap[1];
        r.z = w0 * am[2] + w1 * a0[2] + w2 * ap[2];
        r.w = w0 * am[3] + w1 * a0[3] + w2 * ap[3];
        __stcs(&out4[obase + (long long)o * HW4_], r);
    }
}

// ---------------------------------------------------------------------------
extern "C" void kernel_launch(void* const* d_in, const int* in_sizes, int n_in,
                              void* d_out, int out_size) {
    const float* x      = (const float*)d_in[0];   // [4,32,720,720] f32
    const float* conv_w = (const float*)d_in[1];   // [32,32,3,1] f32
    float* out          = (float*)d_out;           // [4,32,720,720] f32

    (void)in_sizes; (void)n_in; (void)out_size;

    // +1 block: the extra block computes g_W2 from conv_w
    chansum_kernel<<<CHANSUM_BLOCKS + 1, 256>>>(x, conv_w);

    {
        dim3 grid(H_, B_);
        fused_epilogue_kernel<<<grid, 192>>>(out);
    }
}